// round 1
// baseline (speedup 1.0000x reference)
#include <cuda_runtime.h>
#include <math_constants.h>

#define NSEL 11          // KEDGE+1 == KNN+1
#define KNN  10
#define RFAC 100.0f
#define MAXM 8192

// SoA copy of vpoints (72 KB for M=6000) — lives in gmem, cached in L1 per SM.
__device__ float g_vx[MAXM];
__device__ float g_vy[MAXM];
__device__ float g_vz[MAXM];

__global__ void vp_transpose_kernel(const float* __restrict__ vp, int M) {
    int j = blockIdx.x * blockDim.x + threadIdx.x;
    if (j < M) {
        g_vx[j] = vp[3 * j + 0];
        g_vy[j] = vp[3 * j + 1];
        g_vz[j] = vp[3 * j + 2];
    }
}

// ---------------------------------------------------------------------------
// Warp-collective exact top-NSEL scan over M candidates.
// Each lane keeps a sorted (ascending) top-NSEL list in registers; a lazily
// refreshed warp-wide threshold T (= warp-min of per-lane worst) prunes
// candidates that provably cannot reach the global top-NSEL.
// ---------------------------------------------------------------------------
__device__ __forceinline__ void warp_topk_scan(
    float px, float py, float pz, int M, int lane,
    float bd[NSEL], int bi[NSEL])
{
#pragma unroll
    for (int k = 0; k < NSEL; ++k) { bd[k] = CUDART_INF_F; bi[k] = -1; }

    float T = CUDART_INF_F;
    int nsteps = (M + 31) >> 5;
    for (int s = 0; s < nsteps; ++s) {
        int j = (s << 5) + lane;
        float d = CUDART_INF_F;
        if (j < M) {
            float dx = px - g_vx[j];
            float dy = py - g_vy[j];
            float dz = pz - g_vz[j];
            d = dx * dx + dy * dy + dz * dz;
        }
        // d must beat both the warp threshold and this lane's own worst.
        if (d < fminf(T, bd[NSEL - 1])) {
            bd[NSEL - 1] = d;
            bi[NSEL - 1] = j;
#pragma unroll
            for (int k = NSEL - 1; k > 0; --k) {
                if (bd[k] < bd[k - 1]) {
                    float td = bd[k]; bd[k] = bd[k - 1]; bd[k - 1] = td;
                    int   ti = bi[k]; bi[k] = bi[k - 1]; bi[k - 1] = ti;
                }
            }
        }
        if ((s & 15) == 15) {   // refresh prune threshold
            float w = bd[NSEL - 1];
#pragma unroll
            for (int off = 16; off; off >>= 1)
                w = fminf(w, __shfl_xor_sync(0xffffffffu, w, off));
            T = w;
        }
    }
}

// Pop the warp-global minimum across the 32 sorted lists.
// Returns (value in *pm, index in *pidx) to ALL lanes; winner lane shifts.
__device__ __forceinline__ void warp_pop_min(
    int lane, float bd[NSEL], int bi[NSEL], float* pm, int* pidx)
{
    float h = bd[0];
    float m = h;
#pragma unroll
    for (int off = 16; off; off >>= 1)
        m = fminf(m, __shfl_xor_sync(0xffffffffu, m, off));
    unsigned ball = __ballot_sync(0xffffffffu, h == m);
    int win = __ffs(ball) - 1;
    int widx = __shfl_sync(0xffffffffu, bi[0], win);
    if (lane == win) {
#pragma unroll
        for (int k = 0; k < NSEL - 1; ++k) { bd[k] = bd[k + 1]; bi[k] = bi[k + 1]; }
        bd[NSEL - 1] = CUDART_INF_F;
        bi[NSEL - 1] = -1;
    }
    *pm = m;
    *pidx = widx;
}

// ---------------------------------------------------------------------------
// Part A: warp per query. Top-11 neighbors -> Voronoi edge min-distance.
// ---------------------------------------------------------------------------
__global__ void __launch_bounds__(256)
voronoi_query_kernel(const float* __restrict__ q, float* __restrict__ out,
                     int N, int M)
{
    int warp = (blockIdx.x * blockDim.x + threadIdx.x) >> 5;
    int lane = threadIdx.x & 31;
    if (warp >= N) return;

    float qx = q[3 * warp + 0];
    float qy = q[3 * warp + 1];
    float qz = q[3 * warp + 2];

    float bd[NSEL]; int bi[NSEL];
    warp_topk_scan(qx, qy, qz, M, lane, bd, bi);

    float p0x = 0.f, p0y = 0.f, p0z = 0.f;
    float cx = 0.f, cy = 0.f, cz = 0.f;
    float smin = CUDART_INF_F;

    for (int r = 0; r < NSEL; ++r) {
        float m; int widx;
        warp_pop_min(lane, bd, bi, &m, &widx);
        if (r == 0) {
            p0x = g_vx[widx]; p0y = g_vy[widx]; p0z = g_vz[widx];
            cx = qx - p0x; cy = qy - p0y; cz = qz - p0z;
        } else {
            float ex = g_vx[widx] - p0x;
            float ey = g_vy[widx] - p0y;
            float ez = g_vz[widx] - p0z;
            float el2 = ex * ex + ey * ey + ez * ez;
            float el = sqrtf(el2);
            float vl = (cx * ex + cy * ey + cz * ez) / el;
            float t = vl - 0.5f * el;
            smin = fminf(smin, t * t);
        }
    }
    if (lane == 0) out[warp] = smin;
}

// ---------------------------------------------------------------------------
// Part B: warp per vpoint. 10 nearest non-self sq-distances (ascending)
// -> exp(-100*d)/100, written in ascending order (matches top_k layout).
// ---------------------------------------------------------------------------
__global__ void __launch_bounds__(256)
repulsion_kernel(float* __restrict__ out, int N, int M)
{
    int warp = (blockIdx.x * blockDim.x + threadIdx.x) >> 5;
    int lane = threadIdx.x & 31;
    if (warp >= M) return;

    float px = g_vx[warp];
    float py = g_vy[warp];
    float pz = g_vz[warp];

    float bd[NSEL]; int bi[NSEL];
    warp_topk_scan(px, py, pz, M, lane, bd, bi);

    for (int r = 0; r < NSEL; ++r) {
        float m; int widx;
        warp_pop_min(lane, bd, bi, &m, &widx);
        (void)widx;
        if (r >= 1 && lane == 0) {
            out[N + warp * KNN + (r - 1)] = expf(-RFAC * m) * (1.0f / RFAC);
        }
    }
}

extern "C" void kernel_launch(void* const* d_in, const int* in_sizes, int n_in,
                              void* d_out, int out_size)
{
    const float* queries = (const float*)d_in[0];
    const float* vpoints = (const float*)d_in[1];
    float* out = (float*)d_out;

    int N = in_sizes[0] / 3;   // 16384
    int M = in_sizes[1] / 3;   // 6000

    vp_transpose_kernel<<<(M + 255) / 256, 256>>>(vpoints, M);

    // warp per query: 8 warps / 256-thread block
    int blocksA = (N * 32 + 255) / 256;
    voronoi_query_kernel<<<blocksA, 256>>>(queries, out, N, M);

    int blocksB = (M * 32 + 255) / 256;
    repulsion_kernel<<<blocksB, 256>>>(out, N, M);
}

// round 2
// speedup vs baseline: 6.1115x; 6.1115x over previous
#include <cuda_runtime.h>
#include <math_constants.h>

#define NSEL 11          // KEDGE+1 == KNN+1
#define KNN  10
#define RFAC 100.0f
#define MAXM 8192
#define GRID 8
#define NCELLS (GRID*GRID*GRID)
#define H    0.25f
#define INVH 4.0f

// Grid data (device globals — no allocation allowed)
__device__ int    g_cnt[NCELLS];
__device__ int    g_fill[NCELLS];
__device__ int    g_start[NCELLS + 1];
__device__ float4 g_pt[MAXM];      // points sorted by cell, padded to 16B

__device__ __forceinline__ int cell_coord(float x) {
    int c = (int)((x + 1.0f) * INVH);
    return min(GRID - 1, max(0, c));
}

// ---------------------------------------------------------------------------
// Grid build
// ---------------------------------------------------------------------------
__global__ void grid_zero_kernel() {
    int t = threadIdx.x;
    g_cnt[t] = 0;
    g_fill[t] = 0;
}

__global__ void grid_count_kernel(const float* __restrict__ vp, int M) {
    int j = blockIdx.x * blockDim.x + threadIdx.x;
    if (j < M) {
        int cx = cell_coord(vp[3 * j + 0]);
        int cy = cell_coord(vp[3 * j + 1]);
        int cz = cell_coord(vp[3 * j + 2]);
        atomicAdd(&g_cnt[(cz * GRID + cy) * GRID + cx], 1);
    }
}

__global__ void grid_scan_kernel() {
    __shared__ int s[NCELLS];
    int t = threadIdx.x;
    s[t] = g_cnt[t];
    __syncthreads();
    for (int off = 1; off < NCELLS; off <<= 1) {
        int v = (t >= off) ? s[t - off] : 0;
        __syncthreads();
        s[t] += v;
        __syncthreads();
    }
    g_start[t + 1] = s[t];
    if (t == 0) g_start[0] = 0;
}

__global__ void grid_scatter_kernel(const float* __restrict__ vp, int M) {
    int j = blockIdx.x * blockDim.x + threadIdx.x;
    if (j < M) {
        float x = vp[3 * j + 0];
        float y = vp[3 * j + 1];
        float z = vp[3 * j + 2];
        int c = (cell_coord(z) * GRID + cell_coord(y)) * GRID + cell_coord(x);
        int pos = g_start[c] + atomicAdd(&g_fill[c], 1);
        g_pt[pos] = make_float4(x, y, z, 0.0f);
    }
}

// ---------------------------------------------------------------------------
// Warp-collective kNN machinery
// ---------------------------------------------------------------------------
__device__ __forceinline__ void scan_range(
    int beg, int end, float qx, float qy, float qz, int lane,
    float bd[NSEL], int bi[NSEL])
{
    for (int j = beg + lane; j < end; j += 32) {
        float4 p = __ldg(&g_pt[j]);
        float dx = qx - p.x;
        float dy = qy - p.y;
        float dz = qz - p.z;
        float d = fmaf(dx, dx, fmaf(dy, dy, dz * dz));
        if (d < bd[NSEL - 1]) {
            bd[NSEL - 1] = d;
            bi[NSEL - 1] = j;
#pragma unroll
            for (int k = NSEL - 1; k > 0; --k) {
                if (bd[k] < bd[k - 1]) {
                    float td = bd[k]; bd[k] = bd[k - 1]; bd[k - 1] = td;
                    int   ti = bi[k]; bi[k] = bi[k - 1]; bi[k - 1] = ti;
                }
            }
        }
    }
}

// 11 pop rounds; lane r ends up holding rank-r (value in *seed_d, g_pt index in
// *seed_i). Returns the 11th-smallest value (broadcast to all lanes).
__device__ __forceinline__ float warp_merge_seed(
    int lane, float bd[NSEL], int bi[NSEL], float* seed_d, int* seed_i)
{
    float last = CUDART_INF_F;
#pragma unroll
    for (int rnd = 0; rnd < NSEL; ++rnd) {
        float h = bd[0];
        float m = h;
#pragma unroll
        for (int off = 16; off; off >>= 1)
            m = fminf(m, __shfl_xor_sync(0xffffffffu, m, off));
        unsigned ball = __ballot_sync(0xffffffffu, h == m);
        int win = __ffs(ball) - 1;
        int widx = __shfl_sync(0xffffffffu, bi[0], win);
        if (lane == win) {
#pragma unroll
            for (int k = 0; k < NSEL - 1; ++k) { bd[k] = bd[k + 1]; bi[k] = bi[k + 1]; }
            bd[NSEL - 1] = CUDART_INF_F;
            bi[NSEL - 1] = -1;
        }
        if (lane == rnd) { *seed_d = m; *seed_i = widx; }
        last = m;
    }
    return last;
}

// Exact top-NSEL via grid ring expansion. On return lane r (r<NSEL) holds
// rank-r in (seed_d, seed_i), ascending.
__device__ __forceinline__ void grid_topk(
    float qx, float qy, float qz, int lane, float* seed_d, int* seed_i)
{
    int cx = cell_coord(qx);
    int cy = cell_coord(qy);
    int cz = cell_coord(qz);
    int rmax = max(max(cx, GRID - 1 - cx),
               max(max(cy, GRID - 1 - cy), max(cz, GRID - 1 - cz)));

    float bd[NSEL]; int bi[NSEL];
#pragma unroll
    for (int k = 0; k < NSEL; ++k) { bd[k] = CUDART_INF_F; bi[k] = -1; }

    // Ring-1 block (Chebyshev <= 1): 9 contiguous x-rows
    for (int dz = -1; dz <= 1; ++dz) {
        int z = cz + dz;
        if (z < 0 || z >= GRID) continue;
        for (int dy = -1; dy <= 1; ++dy) {
            int y = cy + dy;
            if (y < 0 || y >= GRID) continue;
            int x0 = max(cx - 1, 0), x1 = min(cx + 1, GRID - 1);
            int c0 = (z * GRID + y) * GRID + x0;
            scan_range(g_start[c0], g_start[c0 + (x1 - x0) + 1], qx, qy, qz, lane, bd, bi);
        }
    }

    int r = 1;
    for (;;) {
        *seed_d = CUDART_INF_F;
        *seed_i = -1;
        float m11 = warp_merge_seed(lane, bd, bi, seed_d, seed_i);
        float rr = (float)r * H;
        if (m11 <= rr * rr || r >= rmax) break;

        // reseed lists with current global top-NSEL (lane r holds rank r)
#pragma unroll
        for (int k = 0; k < NSEL; ++k) { bd[k] = CUDART_INF_F; bi[k] = -1; }
        if (lane < NSEL) { bd[0] = *seed_d; bi[0] = *seed_i; }

        // scan shell at Chebyshev distance r+1
        ++r;
        for (int dz = -r; dz <= r; ++dz) {
            int z = cz + dz;
            if (z < 0 || z >= GRID) continue;
            for (int dy = -r; dy <= r; ++dy) {
                int y = cy + dy;
                if (y < 0 || y >= GRID) continue;
                int rowbase = (z * GRID + y) * GRID;
                if (abs(dz) == r || abs(dy) == r) {
                    int x0 = max(cx - r, 0), x1 = min(cx + r, GRID - 1);
                    int c0 = rowbase + x0;
                    scan_range(g_start[c0], g_start[c0 + (x1 - x0) + 1], qx, qy, qz, lane, bd, bi);
                } else {
                    int xl = cx - r, xh = cx + r;
                    if (xl >= 0) {
                        int c = rowbase + xl;
                        scan_range(g_start[c], g_start[c + 1], qx, qy, qz, lane, bd, bi);
                    }
                    if (xh < GRID) {
                        int c = rowbase + xh;
                        scan_range(g_start[c], g_start[c + 1], qx, qy, qz, lane, bd, bi);
                    }
                }
            }
        }
    }
}

// ---------------------------------------------------------------------------
// MODE 0: Part A (Voronoi edge min) — out[q] = sq_min
// MODE 1: Part B (repulsion)       — out[base + q*KNN + (rank-1)]
// ---------------------------------------------------------------------------
template <int MODE>
__global__ void __launch_bounds__(256)
knn_kernel(const float* __restrict__ qarr, float* __restrict__ out,
           int NQ, int base)
{
    int q = (blockIdx.x * blockDim.x + threadIdx.x) >> 5;
    int lane = threadIdx.x & 31;
    if (q >= NQ) return;

    float qx = qarr[3 * q + 0];
    float qy = qarr[3 * q + 1];
    float qz = qarr[3 * q + 2];

    float seed_d; int seed_i;
    grid_topk(qx, qy, qz, lane, &seed_d, &seed_i);

    if (MODE == 0) {
        // lane r holds rank-r neighbor; rank0 = p0
        float4 p = make_float4(0.f, 0.f, 0.f, 0.f);
        if (lane < NSEL && seed_i >= 0) p = g_pt[seed_i];
        float p0x = __shfl_sync(0xffffffffu, p.x, 0);
        float p0y = __shfl_sync(0xffffffffu, p.y, 0);
        float p0z = __shfl_sync(0xffffffffu, p.z, 0);
        float ccx = qx - p0x, ccy = qy - p0y, ccz = qz - p0z;

        float t2 = CUDART_INF_F;
        if (lane >= 1 && lane < NSEL) {
            float ex = p.x - p0x, ey = p.y - p0y, ez = p.z - p0z;
            float el2 = fmaf(ex, ex, fmaf(ey, ey, ez * ez));
            float el = sqrtf(el2);
            float vl = fmaf(ccx, ex, fmaf(ccy, ey, ccz * ez)) / el;
            float t = vl - 0.5f * el;
            t2 = t * t;
        }
#pragma unroll
        for (int off = 16; off; off >>= 1)
            t2 = fminf(t2, __shfl_xor_sync(0xffffffffu, t2, off));
        if (lane == 0) out[q] = t2;
    } else {
        // ranks 1..10 ascending -> exp(-100 d)/100
        if (lane >= 1 && lane < NSEL)
            out[base + q * KNN + (lane - 1)] = expf(-RFAC * seed_d) * (1.0f / RFAC);
    }
}

extern "C" void kernel_launch(void* const* d_in, const int* in_sizes, int n_in,
                              void* d_out, int out_size)
{
    const float* queries = (const float*)d_in[0];
    const float* vpoints = (const float*)d_in[1];
    float* out = (float*)d_out;

    int N = in_sizes[0] / 3;   // 16384
    int M = in_sizes[1] / 3;   // 6000

    grid_zero_kernel<<<1, NCELLS>>>();
    grid_count_kernel<<<(M + 255) / 256, 256>>>(vpoints, M);
    grid_scan_kernel<<<1, NCELLS>>>();
    grid_scatter_kernel<<<(M + 255) / 256, 256>>>(vpoints, M);

    knn_kernel<0><<<(N * 32 + 255) / 256, 256>>>(queries, out, N, 0);
    knn_kernel<1><<<(M * 32 + 255) / 256, 256>>>(vpoints, out, M, N);
}

// round 3
// speedup vs baseline: 8.7688x; 1.4348x over previous
#include <cuda_runtime.h>
#include <math_constants.h>

#define NSEL 11          // KEDGE+1 == KNN+1
#define KNN  10
#define RFAC 100.0f
#define MAXM 8192
#define GRID 10
#define NCELLS (GRID*GRID*GRID)
#define H    0.2f
#define INVH 5.0f
#define CAP  8           // per-lane list capacity (P[fail] ~ 5e-11, see analysis)

__device__ int    g_start[NCELLS + 1];
__device__ float4 g_pt[MAXM];      // points sorted by cell

__device__ __forceinline__ int cell_coord(float x) {
    int c = (int)((x + 1.0f) * INVH);
    return min(GRID - 1, max(0, c));
}

// ---------------------------------------------------------------------------
// Grid build: one block does count -> scan -> scatter entirely in smem.
// ---------------------------------------------------------------------------
__global__ void __launch_bounds__(1024)
build_grid_kernel(const float* __restrict__ vp, int M)
{
    __shared__ int s_cnt[NCELLS];
    __shared__ int s_scan[NCELLS];
    int t = threadIdx.x;

    if (t < NCELLS) s_cnt[t] = 0;
    __syncthreads();

    for (int j = t; j < M; j += blockDim.x) {
        int cx = cell_coord(vp[3 * j + 0]);
        int cy = cell_coord(vp[3 * j + 1]);
        int cz = cell_coord(vp[3 * j + 2]);
        atomicAdd(&s_cnt[(cz * GRID + cy) * GRID + cx], 1);
    }
    __syncthreads();

    if (t < NCELLS) s_scan[t] = s_cnt[t];
    __syncthreads();
    for (int off = 1; off < NCELLS; off <<= 1) {
        int v = 0;
        if (t < NCELLS && t >= off) v = s_scan[t - off];
        __syncthreads();
        if (t < NCELLS) s_scan[t] += v;
        __syncthreads();
    }

    if (t < NCELLS) {
        g_start[t + 1] = s_scan[t];
        s_cnt[t] = s_scan[t] - s_cnt[t];   // exclusive offset = running fill cursor
    }
    if (t == 0) g_start[0] = 0;
    __syncthreads();

    for (int j = t; j < M; j += blockDim.x) {
        float x = vp[3 * j + 0];
        float y = vp[3 * j + 1];
        float z = vp[3 * j + 2];
        int c = (cell_coord(z) * GRID + cell_coord(y)) * GRID + cell_coord(x);
        int pos = atomicAdd(&s_cnt[c], 1);
        g_pt[pos] = make_float4(x, y, z, 0.0f);
    }
}

// ---------------------------------------------------------------------------
// Warp-collective kNN machinery
// ---------------------------------------------------------------------------
__device__ __forceinline__ void scan_range(
    int beg, int end, float qx, float qy, float qz, int lane,
    float bd[CAP], int bi[CAP])
{
    for (int j = beg + lane; j < end; j += 32) {
        float4 p = __ldg(&g_pt[j]);
        float dx = qx - p.x;
        float dy = qy - p.y;
        float dz = qz - p.z;
        float d = fmaf(dx, dx, fmaf(dy, dy, dz * dz));
        if (d < bd[CAP - 1]) {
            bd[CAP - 1] = d;
            bi[CAP - 1] = j;
#pragma unroll
            for (int k = CAP - 1; k > 0; --k) {
                if (bd[k] < bd[k - 1]) {
                    float td = bd[k]; bd[k] = bd[k - 1]; bd[k - 1] = td;
                    int   ti = bi[k]; bi[k] = bi[k - 1]; bi[k - 1] = ti;
                }
            }
        }
    }
}

// 11 pop rounds via REDUX argmin. Lane r (r<NSEL) ends holding rank-r in
// (*seed_d, *seed_i). Returns the 11th-smallest value, broadcast.
__device__ __forceinline__ float warp_merge_seed(
    int lane, float bd[CAP], int bi[CAP], float* seed_d, int* seed_i)
{
    float last = CUDART_INF_F;
#pragma unroll
    for (int rnd = 0; rnd < NSEL; ++rnd) {
        // Pack lane into low 5 bits of the ordered bit pattern (d >= 0).
        unsigned key = (__float_as_uint(bd[0]) & ~31u) | (unsigned)lane;
        unsigned m = __reduce_min_sync(0xffffffffu, key);
        int win = (int)(m & 31u);
        float wval = __shfl_sync(0xffffffffu, bd[0], win);
        int   widx = __shfl_sync(0xffffffffu, bi[0], win);
        if (lane == win) {
#pragma unroll
            for (int k = 0; k < CAP - 1; ++k) { bd[k] = bd[k + 1]; bi[k] = bi[k + 1]; }
            bd[CAP - 1] = CUDART_INF_F;
            bi[CAP - 1] = -1;
        }
        if (lane == rnd) { *seed_d = wval; *seed_i = widx; }
        last = wval;
    }
    return last;
}

// Exact top-NSEL via grid ring expansion. On return lane r (r<NSEL) holds
// rank-r in (seed_d, seed_i), ascending.
__device__ __forceinline__ void grid_topk(
    float qx, float qy, float qz, int lane, float* seed_d, int* seed_i)
{
    int cx = cell_coord(qx);
    int cy = cell_coord(qy);
    int cz = cell_coord(qz);
    int rmax = max(max(cx, GRID - 1 - cx),
               max(max(cy, GRID - 1 - cy), max(cz, GRID - 1 - cz)));

    float bd[CAP]; int bi[CAP];
#pragma unroll
    for (int k = 0; k < CAP; ++k) { bd[k] = CUDART_INF_F; bi[k] = -1; }

    // Ring-1 block (Chebyshev <= 1): contiguous x-rows
    {
        int z0 = max(cz - 1, 0), z1 = min(cz + 1, GRID - 1);
        int y0 = max(cy - 1, 0), y1 = min(cy + 1, GRID - 1);
        int x0 = max(cx - 1, 0), x1 = min(cx + 1, GRID - 1);
        for (int z = z0; z <= z1; ++z)
            for (int y = y0; y <= y1; ++y) {
                int c0 = (z * GRID + y) * GRID + x0;
                scan_range(g_start[c0], g_start[c0 + (x1 - x0) + 1],
                           qx, qy, qz, lane, bd, bi);
            }
    }

    int r = 1;
    for (;;) {
        *seed_d = CUDART_INF_F;
        *seed_i = -1;
        float m11 = warp_merge_seed(lane, bd, bi, seed_d, seed_i);
        float rr = (float)r * H;
        if (m11 <= rr * rr || r >= rmax) break;

        // reseed lists with current global top-NSEL (lane r holds rank r)
#pragma unroll
        for (int k = 0; k < CAP; ++k) { bd[k] = CUDART_INF_F; bi[k] = -1; }
        if (lane < NSEL) { bd[0] = *seed_d; bi[0] = *seed_i; }

        // scan shell at Chebyshev distance r+1
        ++r;
        for (int dz = -r; dz <= r; ++dz) {
            int z = cz + dz;
            if (z < 0 || z >= GRID) continue;
            for (int dy = -r; dy <= r; ++dy) {
                int y = cy + dy;
                if (y < 0 || y >= GRID) continue;
                int rowbase = (z * GRID + y) * GRID;
                if (abs(dz) == r || abs(dy) == r) {
                    int x0 = max(cx - r, 0), x1 = min(cx + r, GRID - 1);
                    int c0 = rowbase + x0;
                    scan_range(g_start[c0], g_start[c0 + (x1 - x0) + 1],
                               qx, qy, qz, lane, bd, bi);
                } else {
                    int xl = cx - r, xh = cx + r;
                    if (xl >= 0) {
                        int c = rowbase + xl;
                        scan_range(g_start[c], g_start[c + 1], qx, qy, qz, lane, bd, bi);
                    }
                    if (xh < GRID) {
                        int c = rowbase + xh;
                        scan_range(g_start[c], g_start[c + 1], qx, qy, qz, lane, bd, bi);
                    }
                }
            }
        }
    }
}

// ---------------------------------------------------------------------------
// Fused kernel: warp w < N  -> Part A (Voronoi edge min), out[w]
//               warp w >= N -> Part B (repulsion), out[N + (w-N)*KNN + rank-1]
// ---------------------------------------------------------------------------
__global__ void __launch_bounds__(256)
knn_fused_kernel(const float* __restrict__ queries,
                 const float* __restrict__ vpoints,
                 float* __restrict__ out, int N, int M)
{
    int w = (blockIdx.x * blockDim.x + threadIdx.x) >> 5;
    int lane = threadIdx.x & 31;
    if (w >= N + M) return;

    bool isA = (w < N);
    int q = isA ? w : (w - N);
    const float* src = isA ? queries : vpoints;

    float qx = src[3 * q + 0];
    float qy = src[3 * q + 1];
    float qz = src[3 * q + 2];

    float seed_d; int seed_i;
    grid_topk(qx, qy, qz, lane, &seed_d, &seed_i);

    if (isA) {
        float4 p = make_float4(0.f, 0.f, 0.f, 0.f);
        if (lane < NSEL && seed_i >= 0) p = g_pt[seed_i];
        float p0x = __shfl_sync(0xffffffffu, p.x, 0);
        float p0y = __shfl_sync(0xffffffffu, p.y, 0);
        float p0z = __shfl_sync(0xffffffffu, p.z, 0);
        float ccx = qx - p0x, ccy = qy - p0y, ccz = qz - p0z;

        float t2 = CUDART_INF_F;
        if (lane >= 1 && lane < NSEL) {
            float ex = p.x - p0x, ey = p.y - p0y, ez = p.z - p0z;
            float el2 = fmaf(ex, ex, fmaf(ey, ey, ez * ez));
            float el = sqrtf(el2);
            float vl = fmaf(ccx, ex, fmaf(ccy, ey, ccz * ez)) / el;
            float t = vl - 0.5f * el;
            t2 = t * t;
        }
        unsigned mbits = __reduce_min_sync(0xffffffffu, __float_as_uint(t2));
        if (lane == 0) out[q] = __uint_as_float(mbits);
    } else {
        if (lane >= 1 && lane < NSEL)
            out[N + q * KNN + (lane - 1)] = expf(-RFAC * seed_d) * (1.0f / RFAC);
    }
}

extern "C" void kernel_launch(void* const* d_in, const int* in_sizes, int n_in,
                              void* d_out, int out_size)
{
    const float* queries = (const float*)d_in[0];
    const float* vpoints = (const float*)d_in[1];
    float* out = (float*)d_out;

    int N = in_sizes[0] / 3;   // 16384
    int M = in_sizes[1] / 3;   // 6000

    build_grid_kernel<<<1, 1024>>>(vpoints, M);

    int totalWarps = N + M;
    knn_fused_kernel<<<(totalWarps * 32 + 255) / 256, 256>>>(queries, vpoints, out, N, M);
}

// round 4
// speedup vs baseline: 9.1694x; 1.0457x over previous
#include <cuda_runtime.h>
#include <math_constants.h>

#define NSEL 11          // KEDGE+1 == KNN+1
#define KNN  10
#define RFAC 100.0f
#define MAXM 8192
#define GRID 10
#define NCELLS (GRID*GRID*GRID)
#define H    0.2f
#define INVH 5.0f
#define CAP  7           // per-lane list capacity (with lane rotation: P[fail]~1e-4 total)

__device__ int    g_start[NCELLS + 1];
__device__ float4 g_pt[MAXM];      // points sorted by cell

__device__ __forceinline__ int cell_coord(float x) {
    int c = (int)((x + 1.0f) * INVH);
    return min(GRID - 1, max(0, c));
}

// ---------------------------------------------------------------------------
// Grid build: one block does count -> scan -> scatter entirely in smem.
// ---------------------------------------------------------------------------
__global__ void __launch_bounds__(1024)
build_grid_kernel(const float* __restrict__ vp, int M)
{
    __shared__ int s_cnt[NCELLS];
    __shared__ int s_scan[NCELLS];
    int t = threadIdx.x;

    if (t < NCELLS) s_cnt[t] = 0;
    __syncthreads();

    for (int j = t; j < M; j += blockDim.x) {
        int cx = cell_coord(vp[3 * j + 0]);
        int cy = cell_coord(vp[3 * j + 1]);
        int cz = cell_coord(vp[3 * j + 2]);
        atomicAdd(&s_cnt[(cz * GRID + cy) * GRID + cx], 1);
    }
    __syncthreads();

    if (t < NCELLS) s_scan[t] = s_cnt[t];
    __syncthreads();
    for (int off = 1; off < NCELLS; off <<= 1) {
        int v = 0;
        if (t < NCELLS && t >= off) v = s_scan[t - off];
        __syncthreads();
        if (t < NCELLS) s_scan[t] += v;
        __syncthreads();
    }

    if (t < NCELLS) {
        g_start[t + 1] = s_scan[t];
        s_cnt[t] = s_scan[t] - s_cnt[t];   // exclusive offset = running fill cursor
    }
    if (t == 0) g_start[0] = 0;
    __syncthreads();

    for (int j = t; j < M; j += blockDim.x) {
        float x = vp[3 * j + 0];
        float y = vp[3 * j + 1];
        float z = vp[3 * j + 2];
        int c = (cell_coord(z) * GRID + cell_coord(y)) * GRID + cell_coord(x);
        int pos = atomicAdd(&s_cnt[c], 1);
        g_pt[pos] = make_float4(x, y, z, 0.0f);
    }
}

// ---------------------------------------------------------------------------
// Warp-collective kNN machinery.
// HASIDX=false drops the index array (part B needs only distances).
// Lane rotation per row spreads winners over all 32 lanes so CAP=7 is safe.
// ---------------------------------------------------------------------------
template <bool HASIDX>
__device__ __forceinline__ void scan_range(
    int beg, int end, int rot, float qx, float qy, float qz, int lane,
    float bd[CAP], int bi[CAP])
{
    int len = end - beg;
    int off = (lane + rot) & 31;
    for (int base = 0; base < len; base += 32) {
        int o = base + off;
        int j = beg + o;
        float d = CUDART_INF_F;
        if (o < len) {
            float4 p = __ldg(&g_pt[j]);
            float dx = qx - p.x;
            float dy = qy - p.y;
            float dz = qz - p.z;
            d = fmaf(dx, dx, fmaf(dy, dy, dz * dz));
        }
        // warp-uniform skip: chain only when some lane actually inserts
        if (__any_sync(0xffffffffu, d < bd[CAP - 1])) {
            if (d < bd[CAP - 1]) {
                bd[CAP - 1] = d;
                if (HASIDX) bi[CAP - 1] = j;
            }
#pragma unroll
            for (int k = CAP - 1; k > 0; --k) {
                if (bd[k] < bd[k - 1]) {
                    float td = bd[k]; bd[k] = bd[k - 1]; bd[k - 1] = td;
                    if (HASIDX) { int ti = bi[k]; bi[k] = bi[k - 1]; bi[k - 1] = ti; }
                }
            }
        }
    }
}

// 11 pop rounds via REDUX argmin (lane id packed into the 5 low bits of the
// ordered float pattern; exact value recovered by shfl from the winner).
// Lane r (r<NSEL) ends holding rank-r in (*seed_d, *seed_i). Returns the
// 11th-smallest (exact), broadcast.
template <bool HASIDX>
__device__ __forceinline__ float warp_merge_seed(
    int lane, float bd[CAP], int bi[CAP], float* seed_d, int* seed_i)
{
    float last = CUDART_INF_F;
#pragma unroll
    for (int rnd = 0; rnd < NSEL; ++rnd) {
        unsigned key = (__float_as_uint(bd[0]) & ~31u) | (unsigned)lane;
        unsigned m = __reduce_min_sync(0xffffffffu, key);
        int win = (int)(m & 31u);
        float wval = __shfl_sync(0xffffffffu, bd[0], win);
        int widx = 0;
        if (HASIDX) widx = __shfl_sync(0xffffffffu, bi[0], win);
        if (lane == win) {
#pragma unroll
            for (int k = 0; k < CAP - 1; ++k) {
                bd[k] = bd[k + 1];
                if (HASIDX) bi[k] = bi[k + 1];
            }
            bd[CAP - 1] = CUDART_INF_F;
            if (HASIDX) bi[CAP - 1] = -1;
        }
        if (lane == rnd) { *seed_d = wval; *seed_i = widx; }
        last = wval;
    }
    return last;
}

// Exact top-NSEL via grid ring expansion. On return lane r (r<NSEL) holds
// rank-r in (seed_d, seed_i), ascending.
template <bool HASIDX>
__device__ __forceinline__ void grid_topk(
    float qx, float qy, float qz, int lane, float* seed_d, int* seed_i)
{
    int cx = cell_coord(qx);
    int cy = cell_coord(qy);
    int cz = cell_coord(qz);
    int rmax = max(max(cx, GRID - 1 - cx),
               max(max(cy, GRID - 1 - cy), max(cz, GRID - 1 - cz)));

    float bd[CAP]; int bi[CAP];
#pragma unroll
    for (int k = 0; k < CAP; ++k) { bd[k] = CUDART_INF_F; bi[k] = -1; }

    int rot = 0;

    // Ring-1 block (Chebyshev <= 1): contiguous x-rows
    {
        int z0 = max(cz - 1, 0), z1 = min(cz + 1, GRID - 1);
        int y0 = max(cy - 1, 0), y1 = min(cy + 1, GRID - 1);
        int x0 = max(cx - 1, 0), x1 = min(cx + 1, GRID - 1);
        for (int z = z0; z <= z1; ++z)
            for (int y = y0; y <= y1; ++y) {
                int c0 = (z * GRID + y) * GRID + x0;
                scan_range<HASIDX>(g_start[c0], g_start[c0 + (x1 - x0) + 1],
                                   rot, qx, qy, qz, lane, bd, bi);
                rot += 5;
            }
    }

    int r = 1;
    for (;;) {
        *seed_d = CUDART_INF_F;
        *seed_i = -1;
        float m11 = warp_merge_seed<HASIDX>(lane, bd, bi, seed_d, seed_i);
        float rr = (float)r * H;
        if (m11 <= rr * rr || r >= rmax) break;

        // reseed lists with current global top-NSEL (lane r holds rank r)
#pragma unroll
        for (int k = 0; k < CAP; ++k) { bd[k] = CUDART_INF_F; bi[k] = -1; }
        if (lane < NSEL) { bd[0] = *seed_d; bi[0] = *seed_i; }

        // scan shell at Chebyshev distance r+1
        ++r;
        for (int dz = -r; dz <= r; ++dz) {
            int z = cz + dz;
            if (z < 0 || z >= GRID) continue;
            for (int dy = -r; dy <= r; ++dy) {
                int y = cy + dy;
                if (y < 0 || y >= GRID) continue;
                int rowbase = (z * GRID + y) * GRID;
                if (abs(dz) == r || abs(dy) == r) {
                    int x0 = max(cx - r, 0), x1 = min(cx + r, GRID - 1);
                    int c0 = rowbase + x0;
                    scan_range<HASIDX>(g_start[c0], g_start[c0 + (x1 - x0) + 1],
                                       rot, qx, qy, qz, lane, bd, bi);
                    rot += 5;
                } else {
                    int xl = cx - r, xh = cx + r;
                    if (xl >= 0) {
                        int c = rowbase + xl;
                        scan_range<HASIDX>(g_start[c], g_start[c + 1],
                                           rot, qx, qy, qz, lane, bd, bi);
                        rot += 5;
                    }
                    if (xh < GRID) {
                        int c = rowbase + xh;
                        scan_range<HASIDX>(g_start[c], g_start[c + 1],
                                           rot, qx, qy, qz, lane, bd, bi);
                        rot += 5;
                    }
                }
            }
        }
    }
}

// ---------------------------------------------------------------------------
// Fused kernel: warp w < N  -> Part A (Voronoi edge min), out[w]
//               warp w >= N -> Part B (repulsion), out[N + (w-N)*KNN + rank-1]
// ---------------------------------------------------------------------------
__global__ void __launch_bounds__(256)
knn_fused_kernel(const float* __restrict__ queries,
                 const float* __restrict__ vpoints,
                 float* __restrict__ out, int N, int M)
{
    int w = (blockIdx.x * blockDim.x + threadIdx.x) >> 5;
    int lane = threadIdx.x & 31;
    if (w >= N + M) return;

    if (w < N) {
        int q = w;
        float qx = queries[3 * q + 0];
        float qy = queries[3 * q + 1];
        float qz = queries[3 * q + 2];

        float seed_d; int seed_i;
        grid_topk<true>(qx, qy, qz, lane, &seed_d, &seed_i);

        float4 p = make_float4(0.f, 0.f, 0.f, 0.f);
        if (lane < NSEL && seed_i >= 0) p = g_pt[seed_i];
        float p0x = __shfl_sync(0xffffffffu, p.x, 0);
        float p0y = __shfl_sync(0xffffffffu, p.y, 0);
        float p0z = __shfl_sync(0xffffffffu, p.z, 0);
        float ccx = qx - p0x, ccy = qy - p0y, ccz = qz - p0z;

        float t2 = CUDART_INF_F;
        if (lane >= 1 && lane < NSEL) {
            float ex = p.x - p0x, ey = p.y - p0y, ez = p.z - p0z;
            float el2 = fmaf(ex, ex, fmaf(ey, ey, ez * ez));
            float inv = rsqrtf(el2);
            float dot = fmaf(ccx, ex, fmaf(ccy, ey, ccz * ez));
            float t = (dot - 0.5f * el2) * inv;   // vl - el/2
            t2 = t * t;
        }
        unsigned mbits = __reduce_min_sync(0xffffffffu, __float_as_uint(t2));
        if (lane == 0) out[q] = __uint_as_float(mbits);
    } else {
        int q = w - N;
        float qx = vpoints[3 * q + 0];
        float qy = vpoints[3 * q + 1];
        float qz = vpoints[3 * q + 2];

        float seed_d; int seed_i;
        grid_topk<false>(qx, qy, qz, lane, &seed_d, &seed_i);

        if (lane >= 1 && lane < NSEL)
            out[N + q * KNN + (lane - 1)] = __expf(-RFAC * seed_d) * (1.0f / RFAC);
    }
}

extern "C" void kernel_launch(void* const* d_in, const int* in_sizes, int n_in,
                              void* d_out, int out_size)
{
    const float* queries = (const float*)d_in[0];
    const float* vpoints = (const float*)d_in[1];
    float* out = (float*)d_out;

    int N = in_sizes[0] / 3;   // 16384
    int M = in_sizes[1] / 3;   // 6000

    build_grid_kernel<<<1, 1024>>>(vpoints, M);

    int totalWarps = N + M;
    knn_fused_kernel<<<(totalWarps * 32 + 255) / 256, 256>>>(queries, vpoints, out, N, M);
}